// round 17
// baseline (speedup 1.0000x reference)
#include <cuda_runtime.h>
#include <cuda_bf16.h>
#include <cstdint>

typedef unsigned long long u64;

// ---------------------------------------------------------------------------
// dilate_block — round 17: cp.async fp32 staging gather (no pf registers),
// inline bf16 hi/lo conversion in the MMA loop, 3 CTAs/SM, depth-2 async
// pipeline over compressed valid taps. Dual launches + fused stats kept.
// ---------------------------------------------------------------------------

static constexpr int MAXR = 640000;
static constexpr int MAXBLK = MAXR / 128 + 2;

__device__ __align__(16) float g_A [MAXR * 64];
__device__ __align__(16) float g_B [MAXR * 64];
__device__ __align__(16) float g_C [MAXR * 64];
__device__ __align__(16) float g_D [MAXR * 64];
__device__ __align__(16) float g_X1[MAXR * 64];
__device__ __align__(16) float g_X2[MAXR * 64];
__device__ __align__(16) float g_X3[MAXR * 64];
__device__ float g_pS[2 * MAXBLK * 64];
__device__ float g_pQ[2 * MAXBLK * 64];
__device__ float g_st[4 * 128];
__device__ unsigned g_tick[2];                          // zero-init, self-resetting
__device__ __align__(16) float g_Wt[3 * 4096];          // down_w packed (fp32 path)
__device__ __align__(16) uint32_t g_Wb[516096];         // conv weights, frag-major, hi/lo interleaved

// ---------------- helpers ----------------
__device__ __forceinline__ uint32_t smem_u32(const void* p) {
    uint32_t a;
    asm("{ .reg .u64 t; cvta.to.shared.u64 t, %1; cvt.u32.u64 %0, t; }" : "=r"(a) : "l"(p));
    return a;
}
__device__ __forceinline__ uint32_t cvt2(float lo, float hi) {
    uint32_t r;
    asm("cvt.rn.bf16x2.f32 %0, %1, %2;" : "=r"(r) : "f"(hi), "f"(lo));
    return r;
}
__device__ __forceinline__ float2 lds64f(uint32_t a) {
    float2 v;
    asm volatile("ld.shared.v2.f32 {%0,%1}, [%2];" : "=f"(v.x), "=f"(v.y) : "r"(a));
    return v;
}
__device__ __forceinline__ void mma_bf16(float d[4], const uint32_t a[4], const uint32_t b[2]) {
    asm volatile(
        "mma.sync.aligned.m16n8k16.row.col.f32.bf16.bf16.f32 "
        "{%0,%1,%2,%3}, {%4,%5,%6,%7}, {%8,%9}, {%0,%1,%2,%3};"
        : "+f"(d[0]), "+f"(d[1]), "+f"(d[2]), "+f"(d[3])
        : "r"(a[0]), "r"(a[1]), "r"(a[2]), "r"(a[3]), "r"(b[0]), "r"(b[1]));
}
__device__ __forceinline__ u64 ffma2(u64 a, u64 b, u64 c) {
    u64 d;
    asm("fma.rn.f32x2 %0, %1, %2, %3;" : "=l"(d) : "l"(a), "l"(b), "l"(c));
    return d;
}

// ---------------------------------------------------------------------------
// weight prep: fp32 [K][CIN][64] -> per tap [kt][nt(8)][lane(32)][hi0,hi1,lo0,lo1]
// ---------------------------------------------------------------------------
struct WPtrs { const float* p[13]; };

__global__ void __launch_bounds__(256)
wprep(WPtrs w, uint32_t* __restrict__ dst)
{
    const int nT[13]   = {9,9,9,9,27,9,9,9,9,9,9,9,9};
    const int cinA[13] = {32,64,32,64,64,64,64,64,64,64,64,64,64};
    const int offW[13] = {0,18432,55296,73728,110592,221184,258048,294912,
                          331776,368640,405504,442368,479232};
    int b = blockIdx.x, c = 0;
    while (b >= nT[c]) { b -= nT[c]; ++c; }
    const int CIN = cinA[c];
    const int KT = CIN / 16;
    const float* src = w.p[c] + (size_t)b * CIN * 64;
    uint16_t* tap = reinterpret_cast<uint16_t*>(dst + offW[c] + (size_t)b * (KT * 1024));
    for (int e = threadIdx.x; e < CIN * 64; e += 256) {
        const int ci = e >> 6, co = e & 63;
        const float x = src[e];
        __nv_bfloat16 hb = __float2bfloat16(x);
        __nv_bfloat16 lb = __float2bfloat16(x - __bfloat162float(hb));
        const int kt = ci >> 4, ck = (ci & 15) >> 1, j = ci & 1;
        const int regb = (ck >= 4) ? 1 : 0;
        const int tt = ck & 3, nt = co >> 3, gg = co & 7;
        const int word = (((kt * 8 + nt) * 32 + (gg * 4 + tt)) * 4) + regb;  // hi at +0/+1
        tap[word * 2 + j]       = *reinterpret_cast<unsigned short*>(&hb);
        tap[(word + 2) * 2 + j] = *reinterpret_cast<unsigned short*>(&lb);   // lo at +2/+3
    }
}

__global__ void wtrans_down(const float* __restrict__ src, float* __restrict__ dst)
{
    const int k = blockIdx.x;
    for (int e = threadIdx.x; e < 4096; e += 256) {
        const int ci = e >> 6, co = e & 63;
        dst[k * 4096 + ((ci >> 2) * 64 + co) * 4 + (ci & 3)] = src[k * 4096 + e];
    }
}

// ---------------------------------------------------------------------------
// conv body: 8 warps x 16 rows per virtual block. cp.async fp32 staging,
// inline bf16 split in the MMA loop, compressed valid-tap pipeline (depth 2).
// Staging layout: 16B chunks at [(c4*16 + row)*16] (c4 = 4-channel group).
// ---------------------------------------------------------------------------
struct ConvArgs {
    const float* in;
    const int* nbr;
    const uint32_t* W;
    float* out;
    float* pS;
    float* pQ;
    float* st;
    const float* bn;
};

template <int KTILES, int KTAPS, bool STATS, bool BN>
__device__ __forceinline__ void conv_body(
    const ConvArgs a, int nIn, int nOut,
    unsigned* tick, int bid, int nBlocks, char* smem)
{
    constexpr int CIN = KTILES * 16;
    constexpr int TAPW = KTILES * 1024;
    constexpr int NF4 = CIN / 8;                // cp.async chunks per lane
    constexpr int STG_BYTES = CIN * 64;         // (CIN/4 chunks)*16 rows*16B

    __shared__ float redS[8][64];
    __shared__ float redQ[8][64];
    __shared__ float s_st[128];
    __shared__ unsigned sball[8][32];
    __shared__ unsigned s_last;

    const uint32_t abase = smem_u32(smem);
    const int t = threadIdx.x;
    const int w = t >> 5;
    const int l = t & 31;
    const int rowBase = bid * 128 + w * 16;

    if (BN) {
        if (t < 128) s_st[t] = a.bn[t];
        __syncthreads();
    }

    const uint32_t stg0 = abase + (uint32_t)(w * 2 + 0) * STG_BYTES;
    const uint32_t stg1 = abase + (uint32_t)(w * 2 + 1) * STG_BYTES;

    const int grow = rowBase + (l >> 1);
    const bool rowOK = (grow < nOut);
    const int part = l & 1;

    auto getj = [&](int k) -> int {
        return rowOK ? __ldg(&a.nbr[(size_t)k * nOut + grow]) : nIn;
    };
    // cp.async gather of tap k into staging buffer (zfill invalid rows)
    auto gather = [&](int k, uint32_t stg) {
        const int j = getj(k);
        const bool v = (j < nIn);
        const float* src = a.in + (size_t)(v ? j : 0) * CIN;
        const int sz = v ? 16 : 0;
        const int row = l >> 1;
#pragma unroll
        for (int i = 0; i < NF4; ++i) {
            const int c4 = part * NF4 + i;
            asm volatile("cp.async.ca.shared.global [%0], [%1], 16, %2;\n"
                         :: "r"(stg + (uint32_t)((c4 * 16 + row) * 16)),
                            "l"(src + c4 * 4), "r"(sz));
        }
        asm volatile("cp.async.commit_group;\n");
    };

    const int r0 = l >> 2;
    const int q = l & 3;

    auto mma_tap = [&](int k, uint32_t stg, float acc[8][4]) {
        float f0 = 1.f, f1 = 1.f;
        if (BN) {
            const unsigned bm = sball[w][k];
            f0 = (float)((bm >> (2 * r0)) & 1u);
            f1 = (float)((bm >> (2 * (r0 + 8))) & 1u);
        }
        const uint32_t* wtap = a.W + (size_t)k * TAPW;
#pragma unroll
        for (int kt = 0; kt < KTILES; ++kt) {
            const int c = kt * 16 + 2 * q;
            const int c4a = c >> 2;
            const uint32_t sub = (uint32_t)((q & 1) * 8);
            float2 v00 = lds64f(stg + (uint32_t)((c4a * 16 + r0) * 16) + sub);
            float2 v10 = lds64f(stg + (uint32_t)((c4a * 16 + r0 + 8) * 16) + sub);
            float2 v01 = lds64f(stg + (uint32_t)(((c4a + 2) * 16 + r0) * 16) + sub);
            float2 v11 = lds64f(stg + (uint32_t)(((c4a + 2) * 16 + r0 + 8) * 16) + sub);
            if (BN) {
                const float m0 = s_st[c],     r0s = s_st[64 + c];
                const float m1 = s_st[c + 1], r1s = s_st[64 + c + 1];
                const float m8 = s_st[c + 8], r8s = s_st[64 + c + 8];
                const float m9 = s_st[c + 9], r9s = s_st[64 + c + 9];
                float x;
                x = (v00.x - m0) * r0s; v00.x = (x > 0.f ? x : 0.01f * x) * f0;
                x = (v00.y - m1) * r1s; v00.y = (x > 0.f ? x : 0.01f * x) * f0;
                x = (v10.x - m0) * r0s; v10.x = (x > 0.f ? x : 0.01f * x) * f1;
                x = (v10.y - m1) * r1s; v10.y = (x > 0.f ? x : 0.01f * x) * f1;
                x = (v01.x - m8) * r8s; v01.x = (x > 0.f ? x : 0.01f * x) * f0;
                x = (v01.y - m9) * r9s; v01.y = (x > 0.f ? x : 0.01f * x) * f0;
                x = (v11.x - m8) * r8s; v11.x = (x > 0.f ? x : 0.01f * x) * f1;
                x = (v11.y - m9) * r9s; v11.y = (x > 0.f ? x : 0.01f * x) * f1;
            }
            uint32_t ah[4], al[4];
            ah[0] = cvt2(v00.x, v00.y);
            ah[1] = cvt2(v10.x, v10.y);
            ah[2] = cvt2(v01.x, v01.y);
            ah[3] = cvt2(v11.x, v11.y);
            al[0] = cvt2(v00.x - __uint_as_float(ah[0] << 16),
                         v00.y - __uint_as_float(ah[0] & 0xFFFF0000u));
            al[1] = cvt2(v10.x - __uint_as_float(ah[1] << 16),
                         v10.y - __uint_as_float(ah[1] & 0xFFFF0000u));
            al[2] = cvt2(v01.x - __uint_as_float(ah[2] << 16),
                         v01.y - __uint_as_float(ah[2] & 0xFFFF0000u));
            al[3] = cvt2(v11.x - __uint_as_float(ah[3] << 16),
                         v11.y - __uint_as_float(ah[3] & 0xFFFF0000u));
#pragma unroll
            for (int nt = 0; nt < 8; ++nt) {
                const uint32_t widx = ((kt * 8 + nt) * 32 + l) * 4;
                const uint4 bv = __ldg(reinterpret_cast<const uint4*>(wtap + widx));
                uint32_t bh[2] = {bv.x, bv.y};
                uint32_t bl[2] = {bv.z, bv.w};
                mma_bf16(acc[nt], ah, bh);
                mma_bf16(acc[nt], al, bh);
                mma_bf16(acc[nt], ah, bl);
            }
        }
    };

    // ---- prologue: batched validity mask + per-tap ballots ----
    unsigned vmask = 0;
#pragma unroll
    for (int c0 = 0; c0 < KTAPS; c0 += 9) {
        int jj[9];
#pragma unroll
        for (int i = 0; i < 9; ++i)
            if (c0 + i < KTAPS) jj[i] = getj(c0 + i);
#pragma unroll
        for (int i = 0; i < 9; ++i)
            if (c0 + i < KTAPS) {
                const unsigned bal = __ballot_sync(0xFFFFFFFFu, jj[i] < nIn);
                if (l == 0) sball[w][c0 + i] = bal;
                if (bal) vmask |= 1u << (c0 + i);
            }
    }
    __syncwarp();

    float acc[8][4];
#pragma unroll
    for (int nt = 0; nt < 8; ++nt)
#pragma unroll
        for (int j = 0; j < 4; ++j) acc[nt][j] = 0.f;

    // ---- compressed valid-tap pipeline (depth 2, cp.async) ----
    unsigned m = vmask;
    int k0 = -1, k1 = -1;
    if (m) { k0 = __ffs(m) - 1; m &= m - 1; }
    if (m) { k1 = __ffs(m) - 1; m &= m - 1; }
    uint32_t b0 = stg0, b1 = stg1;
    if (k0 >= 0) gather(k0, b0);
    if (k1 >= 0) gather(k1, b1);
    while (k0 >= 0) {
        if (k1 >= 0) asm volatile("cp.async.wait_group 1;\n");
        else         asm volatile("cp.async.wait_group 0;\n");
        __syncwarp();
        mma_tap(k0, b0, acc);
        __syncwarp();
        int k2 = -1;
        if (m) { k2 = __ffs(m) - 1; m &= m - 1; }
        if (k2 >= 0) gather(k2, b0);
        const uint32_t tb = b0; b0 = b1; b1 = tb;
        k0 = k1; k1 = k2;
    }

    // ---- epilogue ----
    const int dg = l >> 2, dt = l & 3;
    const int row0 = rowBase + dg;
    const int row1 = row0 + 8;
    if (row0 < nOut) {
        float* o = a.out + (size_t)row0 * 64 + dt * 2;
#pragma unroll
        for (int nt = 0; nt < 8; ++nt)
            *reinterpret_cast<float2*>(o + nt * 8) = make_float2(acc[nt][0], acc[nt][1]);
    }
    if (row1 < nOut) {
        float* o = a.out + (size_t)row1 * 64 + dt * 2;
#pragma unroll
        for (int nt = 0; nt < 8; ++nt)
            *reinterpret_cast<float2*>(o + nt * 8) = make_float2(acc[nt][2], acc[nt][3]);
    }

    if (STATS) {
#pragma unroll
        for (int nt = 0; nt < 8; ++nt) {
#pragma unroll
            for (int j = 0; j < 2; ++j) {
                float ss = acc[nt][j] + acc[nt][j + 2];
                float qq = acc[nt][j] * acc[nt][j] + acc[nt][j + 2] * acc[nt][j + 2];
                ss += __shfl_xor_sync(0xFFFFFFFFu, ss, 4);
                qq += __shfl_xor_sync(0xFFFFFFFFu, qq, 4);
                ss += __shfl_xor_sync(0xFFFFFFFFu, ss, 8);
                qq += __shfl_xor_sync(0xFFFFFFFFu, qq, 8);
                ss += __shfl_xor_sync(0xFFFFFFFFu, ss, 16);
                qq += __shfl_xor_sync(0xFFFFFFFFu, qq, 16);
                if (l < 4) {
                    redS[w][nt * 8 + l * 2 + j] = ss;
                    redQ[w][nt * 8 + l * 2 + j] = qq;
                }
            }
        }
        __syncthreads();
        if (t < 64) {
            float s = 0.f, q2 = 0.f;
#pragma unroll
            for (int ww = 0; ww < 8; ++ww) { s += redS[ww][t]; q2 += redQ[ww][t]; }
            a.pS[(size_t)bid * 64 + t] = s;
            a.pQ[(size_t)bid * 64 + t] = q2;
        }
        __syncthreads();
        __threadfence();
        if (t == 0) s_last = (atomicAdd(tick, 1u) == (unsigned)nBlocks - 1u) ? 1u : 0u;
        __syncthreads();
        if (s_last) {
            __threadfence();
            const int co = t & 63, sub = t >> 6;
            float s = 0.f, q2 = 0.f;
            for (int b = sub; b < nBlocks; b += 4) {
                s += a.pS[(size_t)b * 64 + co];
                q2 += a.pQ[(size_t)b * 64 + co];
            }
            redS[sub][co] = s;
            redQ[sub][co] = q2;
            __syncthreads();
            if (t < 64) {
                const float S = (redS[0][t] + redS[1][t]) + (redS[2][t] + redS[3][t]);
                const float Q = (redQ[0][t] + redQ[1][t]) + (redQ[2][t] + redQ[3][t]);
                const float inv = 1.0f / (float)nOut;
                const float mm = S * inv;
                const float var = Q * inv - mm * mm;
                a.st[t] = mm;
                a.st[64 + t] = rsqrtf(var + 1e-5f);
            }
            __syncthreads();
            if (t == 0) *tick = 0u;
        }
    }
}

// single conv (pool)
template <int KTILES, int KTAPS>
__global__ void __launch_bounds__(256, 3)
mma_conv_single(ConvArgs a, int nIn, int nOut)
{
    extern __shared__ __align__(16) char smem[];
    conv_body<KTILES, KTAPS, false, false>(a, nIn, nOut, nullptr,
                                           blockIdx.x, gridDim.x, smem);
}

// dual conv: blocks [0,gHalf) run a0, [gHalf,2*gHalf) run a1; both emit stats
template <int KTILES, int KTAPS, bool BN>
__global__ void __launch_bounds__(256, 3)
mma_conv_dual(ConvArgs a0, ConvArgs a1, int nIn, int nOut, int gHalf, unsigned* ticks)
{
    extern __shared__ __align__(16) char smem[];
    if (blockIdx.x < (unsigned)gHalf) {
        conv_body<KTILES, KTAPS, true, BN>(a0, nIn, nOut, &ticks[0],
                                           blockIdx.x, gHalf, smem);
    } else {
        conv_body<KTILES, KTAPS, true, BN>(a1, nIn, nOut, &ticks[1],
                                           blockIdx.x - gHalf, gHalf, smem);
    }
}

// ---------------------------------------------------------------------------
__global__ void combine_kernel(const float4* __restrict__ a, const float* __restrict__ sa,
                               const float4* __restrict__ b, const float* __restrict__ sb,
                               float4* __restrict__ o, long long n4)
{
    const long long i = (long long)blockIdx.x * blockDim.x + threadIdx.x;
    if (i >= n4) return;
    const int c = ((int)(i & 15)) * 4;
    float4 va = a[i];
    float4 vb = b[i];
    float4 r;
    float x;
    x = (va.x - sa[c + 0]) * sa[64 + c + 0]; x = x > 0.f ? x : 0.01f * x; r.x = x;
    x = (va.y - sa[c + 1]) * sa[64 + c + 1]; x = x > 0.f ? x : 0.01f * x; r.y = x;
    x = (va.z - sa[c + 2]) * sa[64 + c + 2]; x = x > 0.f ? x : 0.01f * x; r.z = x;
    x = (va.w - sa[c + 3]) * sa[64 + c + 3]; x = x > 0.f ? x : 0.01f * x; r.w = x;
    x = (vb.x - sb[c + 0]) * sb[64 + c + 0]; x = x > 0.f ? x : 0.01f * x; r.x += x;
    x = (vb.y - sb[c + 1]) * sb[64 + c + 1]; x = x > 0.f ? x : 0.01f * x; r.y += x;
    x = (vb.z - sb[c + 2]) * sb[64 + c + 2]; x = x > 0.f ? x : 0.01f * x; r.z += x;
    x = (vb.w - sb[c + 3]) * sb[64 + c + 3]; x = x > 0.f ? x : 0.01f * x; r.w += x;
    o[i] = r;
}

// out[m] = [x1 | x2 | x3] @ down_w  (fp32 FFMA2 path, warp-autonomous)
__global__ void __launch_bounds__(256)
final_kernel(const float* __restrict__ X1, const float* __restrict__ X2,
             const float* __restrict__ X3, const float* __restrict__ Wp,
             float* __restrict__ out, int M)
{
    __shared__ __align__(16) float buf[8][2][8][64];
    const int t = threadIdx.x;
    const int w = t >> 5;
    const int l = t & 31;
    const int rowBase = (blockIdx.x * 8 + w) * 8;
    const int gr = l >> 2;
    const int gp = l & 3;
    const int grow = rowBase + gr;
    const bool rowOK = (grow < M);

    const float* srcs[3] = {X1, X2, X3};
    auto prefetch = [&](int s, int b) {
        const float* src = srcs[s] + (size_t)(rowOK ? grow : 0) * 64;
        const int sz = rowOK ? 16 : 0;
        const uint32_t dbase = (uint32_t)__cvta_generic_to_shared(&buf[w][b][gr][0]);
#pragma unroll
        for (int i = 0; i < 4; ++i) {
            const int c4 = gp + 4 * i;
            asm volatile("cp.async.ca.shared.global [%0], [%1], 16, %2;\n"
                         :: "r"(dbase + c4 * 16), "l"(src + c4 * 4), "r"(sz));
        }
        asm volatile("cp.async.commit_group;\n");
    };

    u64 accA[8], accB[8];
#pragma unroll
    for (int r = 0; r < 8; ++r) { accA[r] = 0ull; accB[r] = 0ull; }

    prefetch(0, 0);
    for (int s = 0; s < 3; ++s) {
        if (s + 1 < 3) {
            prefetch(s + 1, (s + 1) & 1);
            asm volatile("cp.async.wait_group 1;\n");
        } else {
            asm volatile("cp.async.wait_group 0;\n");
        }
        __syncwarp();
        const float* wk = Wp + (size_t)s * (64 * 64);
        const float* frow = &buf[w][s & 1][0][0];
#pragma unroll
        for (int q = 0; q < 16; ++q) {
            const ulonglong2 wa = *reinterpret_cast<const ulonglong2*>(wk + (q * 64 + l) * 4);
            const ulonglong2 wb = *reinterpret_cast<const ulonglong2*>(wk + (q * 64 + l + 32) * 4);
#pragma unroll
            for (int r = 0; r < 8; ++r) {
                const ulonglong2 s2 =
                    *reinterpret_cast<const ulonglong2*>(frow + r * 64 + q * 4);
                accA[r] = ffma2(s2.x, wa.x, accA[r]);
                accA[r] = ffma2(s2.y, wa.y, accA[r]);
                accB[r] = ffma2(s2.x, wb.x, accB[r]);
                accB[r] = ffma2(s2.y, wb.y, accB[r]);
            }
        }
        __syncwarp();
    }
#pragma unroll
    for (int r = 0; r < 8; ++r) {
        const int orow = rowBase + r;
        if (orow < M) {
            out[(size_t)orow * 64 + l] =
                __uint_as_float((unsigned)accA[r]) + __uint_as_float((unsigned)(accA[r] >> 32));
            out[(size_t)orow * 64 + l + 32] =
                __uint_as_float((unsigned)accB[r]) + __uint_as_float((unsigned)(accB[r] >> 32));
        }
    }
}

// ---------------------------------------------------------------------------
extern "C" void kernel_launch(void* const* d_in, const int* in_sizes, int n_in,
                              void* d_out, int out_size)
{
    const float* feats  = (const float*)d_in[0];
    const float* down_w = (const float*)d_in[14];
    const int* n331_1 = (const int*)d_in[15];
    const int* n313_1 = (const int*)d_in[16];
    const int* pool_n = (const int*)d_in[17];
    const int* n331_2 = (const int*)d_in[18];
    const int* n313_2 = (const int*)d_in[19];
    const int* n331_3 = (const int*)d_in[20];
    const int* n313_3 = (const int*)d_in[21];

    const int N = in_sizes[0] / 32;
    const int M = out_size / 64;

    float *A, *B, *C, *D, *X1, *X2, *X3, *pS, *pQ, *st, *Wt;
    uint32_t* Wb;
    unsigned* ticks;
    cudaGetSymbolAddress((void**)&A,  g_A);
    cudaGetSymbolAddress((void**)&B,  g_B);
    cudaGetSymbolAddress((void**)&C,  g_C);
    cudaGetSymbolAddress((void**)&D,  g_D);
    cudaGetSymbolAddress((void**)&X1, g_X1);
    cudaGetSymbolAddress((void**)&X2, g_X2);
    cudaGetSymbolAddress((void**)&X3, g_X3);
    cudaGetSymbolAddress((void**)&pS, g_pS);
    cudaGetSymbolAddress((void**)&pQ, g_pQ);
    cudaGetSymbolAddress((void**)&st, g_st);
    cudaGetSymbolAddress((void**)&Wt, g_Wt);
    cudaGetSymbolAddress((void**)&Wb, g_Wb);
    cudaGetSymbolAddress((void**)&ticks, g_tick);
    float* st0 = st;
    float* st1 = st + 128;
    float* st2 = st + 256;
    float* st3 = st + 384;
    float* pS1 = pS + (size_t)MAXBLK * 64;
    float* pQ1 = pQ + (size_t)MAXBLK * 64;

    const size_t o0 = 0;
    const size_t o1 = 18432;
    const size_t o2 = 55296;
    const size_t o3 = 73728;
    const size_t o4 = 110592;
    const size_t o5 = 221184;
    const size_t o6 = 258048;
    const size_t o7 = 294912;
    const size_t o8 = 331776;
    const size_t o9 = 368640;
    const size_t o10 = 405504;
    const size_t o11 = 442368;
    const size_t o12 = 479232;

    // dynamic smem: fp32 staging (8 warps x 2 bufs)
    const int SM2 = 8 * 2 * (32 * 64);   // 32768
    const int SM4 = 8 * 2 * (64 * 64);   // 65536
    cudaFuncSetAttribute(mma_conv_dual<2, 9, false>,
                         cudaFuncAttributeMaxDynamicSharedMemorySize, SM2);
    cudaFuncSetAttribute(mma_conv_dual<4, 9, false>,
                         cudaFuncAttributeMaxDynamicSharedMemorySize, SM4);
    cudaFuncSetAttribute(mma_conv_dual<4, 9, true>,
                         cudaFuncAttributeMaxDynamicSharedMemorySize, SM4);
    cudaFuncSetAttribute(mma_conv_single<4, 27>,
                         cudaFuncAttributeMaxDynamicSharedMemorySize, SM4);

    WPtrs wp;
    for (int i = 0; i < 13; ++i) wp.p[i] = (const float*)d_in[1 + i];
    wprep<<<135, 256>>>(wp, Wb);
    wtrans_down<<<3, 256>>>(down_w, Wt);

    const int gN = (N + 127) / 128;
    const int gM = (M + 127) / 128;
    const long long n4N = (long long)N * 16;
    const long long n4M = (long long)M * 16;
    const int gbN = (int)((n4N + 255) / 256);
    const int gbM = (int)((n4M + 255) / 256);
    const int gMf = (M + 63) / 64;

    auto CA = [](const float* in, const int* nbr, const uint32_t* W, float* out,
                 float* ps, float* pq, float* stp, const float* bn) {
        ConvArgs a;
        a.in = in; a.nbr = nbr; a.W = W; a.out = out;
        a.pS = ps; a.pQ = pq; a.st = stp; a.bn = bn;
        return a;
    };

    // ---- block 1 (N rows, 32 -> 64) ----
    mma_conv_dual<2, 9, false><<<2 * gN, 256, SM2>>>(
        CA(feats, n331_1, Wb + o0, A, pS,  pQ,  st0, nullptr),
        CA(feats, n313_1, Wb + o2, C, pS1, pQ1, st2, nullptr),
        N, N, gN, ticks);
    mma_conv_dual<4, 9, true><<<2 * gN, 256, SM4>>>(
        CA(A, n313_1, Wb + o1, B, pS,  pQ,  st1, st0),
        CA(C, n331_1, Wb + o3, D, pS1, pQ1, st3, st2),
        N, N, gN, ticks);
    combine_kernel<<<gbN, 256>>>((const float4*)D, st3, (const float4*)B, st1,
                                 (float4*)C, n4N);

    // ---- pool (K=27): C (N rows) -> X1 (M rows) ----
    mma_conv_single<4, 27><<<gM, 256, SM4>>>(
        CA(C, pool_n, Wb + o4, X1, nullptr, nullptr, nullptr, nullptr), N, M);

    // ---- block 2 (M rows, dilation 2) ----
    mma_conv_dual<4, 9, false><<<2 * gM, 256, SM4>>>(
        CA(X1, n331_2, Wb + o5, A, pS,  pQ,  st0, nullptr),
        CA(X1, n313_2, Wb + o7, C, pS1, pQ1, st2, nullptr),
        M, M, gM, ticks);
    mma_conv_dual<4, 9, true><<<2 * gM, 256, SM4>>>(
        CA(A, n313_2, Wb + o6, B, pS,  pQ,  st1, st0),
        CA(C, n331_2, Wb + o8, D, pS1, pQ1, st3, st2),
        M, M, gM, ticks);
    combine_kernel<<<gbM, 256>>>((const float4*)D, st3, (const float4*)B, st1,
                                 (float4*)X2, n4M);

    // ---- block 3 (M rows, dilation 3) ----
    mma_conv_dual<4, 9, false><<<2 * gM, 256, SM4>>>(
        CA(X2, n331_3, Wb + o9,  A, pS,  pQ,  st0, nullptr),
        CA(X2, n313_3, Wb + o11, C, pS1, pQ1, st2, nullptr),
        M, M, gM, ticks);
    mma_conv_dual<4, 9, true><<<2 * gM, 256, SM4>>>(
        CA(A, n313_3, Wb + o10, B, pS,  pQ,  st1, st0),
        CA(C, n331_3, Wb + o12, D, pS1, pQ1, st3, st2),
        M, M, gM, ticks);
    combine_kernel<<<gbM, 256>>>((const float4*)D, st3, (const float4*)B, st1,
                                 (float4*)X3, n4M);

    // ---- final 1x1 fuse ----
    final_kernel<<<gMf, 256>>>(X1, X2, X3, Wt, (float*)d_out, M);
}